// round 15
// baseline (speedup 1.0000x reference)
#include <cuda_runtime.h>
#include <cuda_fp16.h>
#include <math.h>

#define NU 100000
#define NI 50000
#define NN (NU + NI)            // 150000 nodes
#define DIM 64
#define NE 1250000
#define NALL (NN * DIM)         // 9,600,000 elements per buffer
#define NV8 (NALL / 8)          // 1,200,000 8-element vector units

#define SCAN_B 1024
#define NBLK ((NN + SCAN_B - 1) / SCAN_B)   // 147
#define NBIN 256

// Scratch (allocation-free): ~64 MB of __device__ globals.
__device__ __align__(16) __half g_s[3][NALL + DIM]; // pre-scaled buffers + sentinel row
__device__ int   g_degi[NN];      // in-degree
__device__ int   g_rowstart[NN];  // CSR cursor: start -> end (post-fill)
__device__ float g_rns[NN];       // 1/sqrt(deg) or 0
__device__ float g_inv[NN];       // sqrt(deg) or 0
__device__ int   g_ctr;           // global range allocator
__device__ int   g_csr[NE];       // src*64 (or NN*64 sentinel)
__device__ int   g_hist[NBIN];    // degree histogram (clamped)
__device__ int   g_cursor[NBIN];  // bin cursors (start -> end)
__device__ int   g_perm[NN];      // rows in degree-sorted order

// ---------------------------------------------------------------------------
// K0: zero degree, allocator, histogram, and sentinel rows.
__global__ void k_zero() {
    int i = blockIdx.x * blockDim.x + threadIdx.x;
    if (i < NN) g_degi[i] = 0;
    if (i < NBIN) g_hist[i] = 0;
    if (i == 0) g_ctr = 0;
    if (i < DIM) {
        g_s[0][NALL + i] = __float2half_rn(0.0f);
        g_s[1][NALL + i] = __float2half_rn(0.0f);
        g_s[2][NALL + i] = __float2half_rn(0.0f);
    }
}

// K1: in-degree. edge_index is int32 (JAX x64-off). Bounds-guarded.
__global__ void k_deg(const int* __restrict__ ei) {
    int e = blockIdx.x * blockDim.x + threadIdx.x;
    if (e >= NE) return;
    int dst = ei[NE + e];
    if ((unsigned)dst < (unsigned)NN) atomicAdd(&g_degi[dst], 1);
}

// K2: CSR range allocation (shuffle block-scan + one atomic per block),
// rns/inv precompute, and smem-aggregated degree histogram.
__global__ void k_alloc() {
    __shared__ int warpsum[32];
    __shared__ int s_base;
    __shared__ int sh_hist[NBIN];
    int i = blockIdx.x * SCAN_B + threadIdx.x;
    int lane = threadIdx.x & 31;
    int wid  = threadIdx.x >> 5;
    int v = (i < NN) ? g_degi[i] : 0;
    if (i < NN) {
        g_rns[i] = (v > 0) ? rsqrtf((float)v) : 0.0f;
        g_inv[i] = (v > 0) ? sqrtf((float)v)  : 0.0f;
    }
    if (threadIdx.x < NBIN) sh_hist[threadIdx.x] = 0;
    __syncthreads();
    if (i < NN) atomicAdd(&sh_hist[min(v, NBIN - 1)], 1);
    int x = v;                                   // inclusive warp scan
    #pragma unroll
    for (int off = 1; off < 32; off <<= 1) {
        int t = __shfl_up_sync(0xFFFFFFFFu, x, off);
        if (lane >= off) x += t;
    }
    if (lane == 31) warpsum[wid] = x;
    __syncthreads();
    if (threadIdx.x < 32) {
        int w = warpsum[threadIdx.x];
        int y = w;
        #pragma unroll
        for (int off = 1; off < 32; off <<= 1) {
            int t = __shfl_up_sync(0xFFFFFFFFu, y, off);
            if (threadIdx.x >= off) y += t;
        }
        warpsum[threadIdx.x] = y - w;            // exclusive
        if (threadIdx.x == 31) s_base = atomicAdd(&g_ctr, y);
    }
    __syncthreads();
    if (i < NN) g_rowstart[i] = s_base + warpsum[wid] + (x - v);
    if (threadIdx.x < NBIN && sh_hist[threadIdx.x])
        atomicAdd(&g_hist[threadIdx.x], sh_hist[threadIdx.x]);
}

// K3: exclusive scan of the 256 bin counts -> g_cursor (bin starts).
__global__ void k_binscan() {
    __shared__ int wsum[8];
    int t = threadIdx.x;
    int lane = t & 31, w = t >> 5;
    int v = g_hist[t];
    int x = v;
    #pragma unroll
    for (int off = 1; off < 32; off <<= 1) {
        int y = __shfl_up_sync(0xFFFFFFFFu, x, off);
        if (lane >= off) x += y;
    }
    if (lane == 31) wsum[w] = x;
    __syncthreads();
    if (t == 0) { int run = 0; for (int j = 0; j < 8; j++) { int c = wsum[j]; wsum[j] = run; run += c; } }
    __syncthreads();
    g_cursor[t] = wsum[w] + x - v;               // exclusive
}

// K4: FUSED perm-fill + CSR-fill + pre-scale.
//  - perm side (tid < NN): block-aggregated counting-sort scatter: smem rank
//    per bin, ONE global atomic per (block,bin) -> no modal-bin serialization.
//  - fill side (tid < NE): CSR fill, random L2 atomics.
//  - scale side (tid < NV8): s0 = fp16(rns*emb), 8 elems/thread, vectorized.
__global__ void k_fillscale(const int* __restrict__ ei,
                            const float* __restrict__ uw,
                            const float* __restrict__ iw) {
    __shared__ int sh_cnt[NBIN];
    __shared__ int sh_base[NBIN];
    int tid = blockIdx.x * blockDim.x + threadIdx.x;

    // --- perm side (cheap, fully synchronized up front) ---
    if (threadIdx.x < NBIN) sh_cnt[threadIdx.x] = 0;
    __syncthreads();
    int d = -1, rank = 0;
    if (tid < NN) { d = min(g_degi[tid], NBIN - 1); rank = atomicAdd(&sh_cnt[d], 1); }
    __syncthreads();
    if (threadIdx.x < NBIN) {
        int c = sh_cnt[threadIdx.x];
        sh_base[threadIdx.x] = c ? atomicAdd(&g_cursor[threadIdx.x], c) : 0;
    }
    __syncthreads();
    if (tid < NN) g_perm[sh_base[d] + rank] = tid;

    // --- CSR fill side ---
    if (tid < NE) {
        int src = ei[tid];
        int dst = ei[NE + tid];
        if ((unsigned)dst < (unsigned)NN) {      // consistent with deg guard
            int soff = ((unsigned)src < (unsigned)NN) ? (src << 6) : (NN << 6);
            int pos = atomicAdd(&g_rowstart[dst], 1);
            g_csr[pos] = soff;
        }
    }
    // --- pre-scale side ---
    if (tid < NV8) {
        int base = tid << 3;                     // 8 elems, one row
        int row  = base >> 6;
        float r = g_rns[row];
        const float* emb = (row < NU) ? &uw[base] : &iw[base - NU * DIM];
        float4 e0 = *reinterpret_cast<const float4*>(emb);
        float4 e1 = *reinterpret_cast<const float4*>(emb + 4);
        __half2 h0 = __floats2half2_rn(r * e0.x, r * e0.y);
        __half2 h1 = __floats2half2_rn(r * e0.z, r * e0.w);
        __half2 h2 = __floats2half2_rn(r * e1.x, r * e1.y);
        __half2 h3 = __floats2half2_rn(r * e1.z, r * e1.w);
        uint4 o;
        o.x = *reinterpret_cast<unsigned*>(&h0);
        o.y = *reinterpret_cast<unsigned*>(&h1);
        o.z = *reinterpret_cast<unsigned*>(&h2);
        o.w = *reinterpret_cast<unsigned*>(&h3);
        *reinterpret_cast<uint4*>(&g_s[0][base]) = o;
    }
}

// Pure-sum edge body: one uint4 = 8 halves, half2 accumulate (4 HADD2).
#define EDGE(S, A0, A1, A2, A3) {                                          \
    uint4 r_ = *reinterpret_cast<const uint4*>(&in[(S) + le]);             \
    A0 = __hadd2(A0, *reinterpret_cast<__half2*>(&r_.x));                  \
    A1 = __hadd2(A1, *reinterpret_cast<__half2*>(&r_.y));                  \
    A2 = __hadd2(A2, *reinterpret_cast<__half2*>(&r_.z));                  \
    A3 = __hadd2(A3, *reinterpret_cast<__half2*>(&r_.w)); }

// K5/6: pull layer in degree-sorted order (perm) -> warps get 4 equal-degree
// rows, no divergence waste. 8 lanes per row, fp32 epilogue, fp16 store.
__global__ void k_gather(int lin, int lout) {
    int gi = blockIdx.x * 32 + (threadIdx.x >> 3);
    if (gi >= NN) return;
    int g = g_perm[gi];
    int le = (threadIdx.x & 7) << 3;
    const __half* __restrict__ in = g_s[lin];
    int end = g_rowstart[g];
    int p   = end - g_degi[g];
    __half2 z = __float2half2_rn(0.0f);
    __half2 pA0=z,pA1=z,pA2=z,pA3=z, pB0=z,pB1=z,pB2=z,pB3=z;
    for (; p + 4 <= end; p += 4) {
        int s0 = g_csr[p],     s1 = g_csr[p + 1];
        int s2 = g_csr[p + 2], s3 = g_csr[p + 3];
        EDGE(s0, pA0, pA1, pA2, pA3) EDGE(s1, pB0, pB1, pB2, pB3)
        EDGE(s2, pA0, pA1, pA2, pA3) EDGE(s3, pB0, pB1, pB2, pB3)
    }
    for (; p < end; ++p) { int s0 = g_csr[p]; EDGE(s0, pA0, pA1, pA2, pA3) }
    float r = g_rns[g]; float r2 = r * r;
    float2 fA, fB;
    fA = __half22float2(pA0); fB = __half22float2(pB0);
    __half2 o0 = __floats2half2_rn(r2 * (fA.x + fB.x), r2 * (fA.y + fB.y));
    fA = __half22float2(pA1); fB = __half22float2(pB1);
    __half2 o1 = __floats2half2_rn(r2 * (fA.x + fB.x), r2 * (fA.y + fB.y));
    fA = __half22float2(pA2); fB = __half22float2(pB2);
    __half2 o2 = __floats2half2_rn(r2 * (fA.x + fB.x), r2 * (fA.y + fB.y));
    fA = __half22float2(pA3); fB = __half22float2(pB3);
    __half2 o3 = __floats2half2_rn(r2 * (fA.x + fB.x), r2 * (fA.y + fB.y));
    uint4 o;
    o.x = *reinterpret_cast<unsigned*>(&o0);
    o.y = *reinterpret_cast<unsigned*>(&o1);
    o.z = *reinterpret_cast<unsigned*>(&o2);
    o.w = *reinterpret_cast<unsigned*>(&o3);
    *reinterpret_cast<uint4*>(&g_s[lout][(g << 6) + le]) = o;
}

// K7: layer-3 gather (degree-sorted) fused with final average.
// out = 0.25*(emb_fp32 + inv*(s1+s2) + rns*t3); out layout [all;all].
__global__ void k_gather_final(const float* __restrict__ uw,
                               const float* __restrict__ iw,
                               float* __restrict__ out) {
    int gi = blockIdx.x * 32 + (threadIdx.x >> 3);
    if (gi >= NN) return;
    int g = g_perm[gi];
    int le = (threadIdx.x & 7) << 3;
    const __half* __restrict__ in = g_s[2];
    int end = g_rowstart[g];
    int p   = end - g_degi[g];
    __half2 z = __float2half2_rn(0.0f);
    __half2 pA0=z,pA1=z,pA2=z,pA3=z, pB0=z,pB1=z,pB2=z,pB3=z;
    for (; p + 4 <= end; p += 4) {
        int s0 = g_csr[p],     s1 = g_csr[p + 1];
        int s2 = g_csr[p + 2], s3 = g_csr[p + 3];
        EDGE(s0, pA0, pA1, pA2, pA3) EDGE(s1, pB0, pB1, pB2, pB3)
        EDGE(s2, pA0, pA1, pA2, pA3) EDGE(s3, pB0, pB1, pB2, pB3)
    }
    for (; p < end; ++p) { int s0 = g_csr[p]; EDGE(s0, pA0, pA1, pA2, pA3) }

    float r   = g_rns[g];
    float inv = g_inv[g];
    int i = (g << 6) + le;
    const float* emb = (g < NU) ? &uw[i] : &iw[i - NU * DIM];
    float4 e0 = *reinterpret_cast<const float4*>(emb);
    float4 e1 = *reinterpret_cast<const float4*>(emb + 4);
    uint4 r1 = *reinterpret_cast<const uint4*>(&g_s[1][i]);
    uint4 r2 = *reinterpret_cast<const uint4*>(&g_s[2][i]);
    float2 s1a = __half22float2(*reinterpret_cast<__half2*>(&r1.x));
    float2 s1b = __half22float2(*reinterpret_cast<__half2*>(&r1.y));
    float2 s1c = __half22float2(*reinterpret_cast<__half2*>(&r1.z));
    float2 s1d = __half22float2(*reinterpret_cast<__half2*>(&r1.w));
    float2 s2a = __half22float2(*reinterpret_cast<__half2*>(&r2.x));
    float2 s2b = __half22float2(*reinterpret_cast<__half2*>(&r2.y));
    float2 s2c = __half22float2(*reinterpret_cast<__half2*>(&r2.z));
    float2 s2d = __half22float2(*reinterpret_cast<__half2*>(&r2.w));
    float2 tA, tB;
    tA = __half22float2(pA0); tB = __half22float2(pB0);
    float t0 = tA.x + tB.x, t1 = tA.y + tB.y;
    tA = __half22float2(pA1); tB = __half22float2(pB1);
    float t2 = tA.x + tB.x, t3 = tA.y + tB.y;
    tA = __half22float2(pA2); tB = __half22float2(pB2);
    float t4 = tA.x + tB.x, t5 = tA.y + tB.y;
    tA = __half22float2(pA3); tB = __half22float2(pB3);
    float t6 = tA.x + tB.x, t7 = tA.y + tB.y;
    float4 v0 = make_float4(0.25f * (e0.x + inv * (s1a.x + s2a.x) + r * t0),
                            0.25f * (e0.y + inv * (s1a.y + s2a.y) + r * t1),
                            0.25f * (e0.z + inv * (s1b.x + s2b.x) + r * t2),
                            0.25f * (e0.w + inv * (s1b.y + s2b.y) + r * t3));
    float4 v1 = make_float4(0.25f * (e1.x + inv * (s1c.x + s2c.x) + r * t4),
                            0.25f * (e1.y + inv * (s1c.y + s2c.y) + r * t5),
                            0.25f * (e1.z + inv * (s1d.x + s2d.x) + r * t6),
                            0.25f * (e1.w + inv * (s1d.y + s2d.y) + r * t7));
    *reinterpret_cast<float4*>(&out[i])            = v0;
    *reinterpret_cast<float4*>(&out[i + 4])        = v1;
    *reinterpret_cast<float4*>(&out[NALL + i])     = v0;
    *reinterpret_cast<float4*>(&out[NALL + i + 4]) = v1;
}

extern "C" void kernel_launch(void* const* d_in, const int* in_sizes, int n_in,
                              void* d_out, int out_size) {
    const int*   ei = (const int*)d_in[0];      // [2, NE] int32
    const float* uw = (const float*)d_in[1];    // [NU, 64]
    const float* iw = (const float*)d_in[2];    // [NI, 64]
    float*      out = (float*)d_out;            // [2*NALL] floats

    const int T = 256;
    int g_edge = (NE + T - 1) / T;              // covers fill/scale/perm sides
    int g_node = (NN + T - 1) / T;
    int g_gath = (NN + 31) / 32;                // 32 rows per 256-thread block

    k_zero<<<g_node, T>>>();
    k_deg<<<g_edge, T>>>(ei);
    k_alloc<<<NBLK, SCAN_B>>>();
    k_binscan<<<1, NBIN>>>();
    k_fillscale<<<g_edge, T>>>(ei, uw, iw);

    k_gather<<<g_gath, T>>>(0, 1);              // layer 1: s0 -> s1
    k_gather<<<g_gath, T>>>(1, 2);              // layer 2: s1 -> s2
    k_gather_final<<<g_gath, T>>>(uw, iw, out); // layer 3 + average + dup
}